// round 1
// baseline (speedup 1.0000x reference)
#include <cuda_runtime.h>

#define NN 200000
#define NE 6400000
#define AF 82
#define HID 10
#define ED 6
#define PSTR 12   // padded row stride for P and agg (16B-friendly)

// Scratch (static __device__ arrays; allocation-free per harness rules)
__device__ __align__(16) float g_h[NN * HID];     // current hidden state
__device__ __align__(16) float g_P[NN * PSTR];    // P = h @ Wg[0:10]  (per-node precompute)
__device__ __align__(16) float g_agg[NN * PSTR];  // scatter-sum accumulator

__device__ __forceinline__ float lrelu(float x) { return x > 0.f ? x : 0.1f * x; }

// ---------------------------------------------------------------------------
// h = lrelu(vertex @ Wi);  P = h @ Wg[0:10]
// 128 nodes per block, vertex rows staged coalesced through smem.
// ---------------------------------------------------------------------------
__global__ void __launch_bounds__(128) init_kernel(const float* __restrict__ vertex,
                                                   const float* __restrict__ Wi,  // [82,10]
                                                   const float* __restrict__ Wg)  // [16,10]
{
    __shared__ float sv[128 * AF];
    __shared__ float sWi[AF * HID];
    __shared__ float sWgh[HID * HID];
    const int tid = threadIdx.x;
    const int base = blockIdx.x * 128;

    for (int i = tid; i < AF * HID; i += 128) sWi[i] = Wi[i];
    for (int i = tid; i < HID * HID; i += 128) sWgh[i] = Wg[i];

    const int nrows = min(128, NN - base);
    const int total = nrows * AF;
    const float* vsrc = vertex + (size_t)base * AF;
    for (int i = tid; i < total; i += 128) sv[i] = vsrc[i];
    __syncthreads();

    if (tid < nrows) {
        const int node = base + tid;
        float acc[HID];
#pragma unroll
        for (int j = 0; j < HID; j++) acc[j] = 0.f;
        const float* row = &sv[tid * AF];
#pragma unroll 2
        for (int k = 0; k < AF; k++) {
            const float v = row[k];
#pragma unroll
            for (int j = 0; j < HID; j++) acc[j] += v * sWi[k * HID + j];
        }
        float h[HID];
#pragma unroll
        for (int j = 0; j < HID; j++) {
            h[j] = lrelu(acc[j]);
            g_h[node * HID + j] = h[j];
        }
        float p[HID];
#pragma unroll
        for (int j = 0; j < HID; j++) p[j] = 0.f;
#pragma unroll
        for (int k = 0; k < HID; k++) {
#pragma unroll
            for (int j = 0; j < HID; j++) p[j] += h[k] * sWgh[k * HID + j];
        }
#pragma unroll
        for (int j = 0; j < HID; j++) g_P[node * PSTR + j] = p[j];
    }
}

// ---------------------------------------------------------------------------
// Zero agg (vectorized)
// ---------------------------------------------------------------------------
__global__ void zero_agg_kernel() {
    const int i = blockIdx.x * blockDim.x + threadIdx.x;
    const int n4 = NN * PSTR / 4;
    if (i < n4) reinterpret_cast<float4*>(g_agg)[i] = make_float4(0.f, 0.f, 0.f, 0.f);
}

// ---------------------------------------------------------------------------
// Per-edge: msg = lrelu(P[src] + ef @ Wg[10:16]); red-add into agg[dst]
// Grid-stride; edge-part weights held in registers (loaded once per thread).
// ---------------------------------------------------------------------------
__global__ void __launch_bounds__(256) edge_kernel(const float* __restrict__ ef,
                                                   const int* __restrict__ src,
                                                   const int* __restrict__ dst,
                                                   const float* __restrict__ Wg)
{
    float w[ED][HID];
#pragma unroll
    for (int k = 0; k < ED; k++)
#pragma unroll
        for (int j = 0; j < HID; j++) w[k][j] = __ldg(&Wg[(HID + k) * HID + j]);

    const int stride = gridDim.x * blockDim.x;
    for (int e = blockIdx.x * blockDim.x + threadIdx.x; e < NE; e += stride) {
        const int s = src[e];
        const int d = dst[e];

        const float2* efp = reinterpret_cast<const float2*>(ef + (size_t)e * ED);
        const float2 f0 = efp[0], f1 = efp[1], f2 = efp[2];
        const float efv[ED] = {f0.x, f0.y, f1.x, f1.y, f2.x, f2.y};

        const float* Pr = g_P + (size_t)s * PSTR;
        const float4 p0 = *reinterpret_cast<const float4*>(Pr);
        const float4 p1 = *reinterpret_cast<const float4*>(Pr + 4);
        const float2 p2 = *reinterpret_cast<const float2*>(Pr + 8);

        float acc[HID] = {p0.x, p0.y, p0.z, p0.w, p1.x, p1.y, p1.z, p1.w, p2.x, p2.y};
#pragma unroll
        for (int k = 0; k < ED; k++)
#pragma unroll
            for (int j = 0; j < HID; j++) acc[j] += efv[k] * w[k][j];
#pragma unroll
        for (int j = 0; j < HID; j++) acc[j] = lrelu(acc[j]);

        float* ap = g_agg + (size_t)d * PSTR;
        asm volatile("red.global.add.v4.f32 [%0], {%1,%2,%3,%4};" ::
                         "l"(ap), "f"(acc[0]), "f"(acc[1]), "f"(acc[2]), "f"(acc[3])
                     : "memory");
        asm volatile("red.global.add.v4.f32 [%0], {%1,%2,%3,%4};" ::
                         "l"(ap + 4), "f"(acc[4]), "f"(acc[5]), "f"(acc[6]), "f"(acc[7])
                     : "memory");
        asm volatile("red.global.add.v2.f32 [%0], {%1,%2};" ::
                         "l"(ap + 8), "f"(acc[8]), "f"(acc[9])
                     : "memory");
    }
}

// ---------------------------------------------------------------------------
// h_new = lrelu(concat(h, agg) @ Wu); optionally P = h_new @ Wg[0:10]
// Final layer writes into d_out (stride 10), else back into g_h.
// ---------------------------------------------------------------------------
__global__ void __launch_bounds__(256) update_kernel(const float* __restrict__ Wu,  // [20,10]
                                                     const float* __restrict__ Wg,  // [16,10]
                                                     float* __restrict__ final_out,
                                                     int is_final)
{
    __shared__ float sWu[2 * HID * HID];
    __shared__ float sWgh[HID * HID];
    const int tid = threadIdx.x;
    for (int i = tid; i < 2 * HID * HID; i += blockDim.x) sWu[i] = Wu[i];
    for (int i = tid; i < HID * HID; i += blockDim.x) sWgh[i] = Wg[i];
    __syncthreads();

    const int n = blockIdx.x * blockDim.x + tid;
    if (n >= NN) return;

    float hv[HID];
#pragma unroll
    for (int j = 0; j < HID; j++) hv[j] = g_h[n * HID + j];

    const float* ar = g_agg + (size_t)n * PSTR;
    const float4 a0 = *reinterpret_cast<const float4*>(ar);
    const float4 a1 = *reinterpret_cast<const float4*>(ar + 4);
    const float2 a2 = *reinterpret_cast<const float2*>(ar + 8);
    const float av[HID] = {a0.x, a0.y, a0.z, a0.w, a1.x, a1.y, a1.z, a1.w, a2.x, a2.y};

    float acc[HID];
#pragma unroll
    for (int j = 0; j < HID; j++) acc[j] = 0.f;
#pragma unroll
    for (int k = 0; k < HID; k++) {
#pragma unroll
        for (int j = 0; j < HID; j++) acc[j] += hv[k] * sWu[k * HID + j];
    }
#pragma unroll
    for (int k = 0; k < HID; k++) {
#pragma unroll
        for (int j = 0; j < HID; j++) acc[j] += av[k] * sWu[(HID + k) * HID + j];
    }

    float hn[HID];
#pragma unroll
    for (int j = 0; j < HID; j++) hn[j] = lrelu(acc[j]);

    if (is_final) {
#pragma unroll
        for (int j = 0; j < HID; j++) final_out[(size_t)n * HID + j] = hn[j];
    } else {
#pragma unroll
        for (int j = 0; j < HID; j++) g_h[n * HID + j] = hn[j];
        float p[HID];
#pragma unroll
        for (int j = 0; j < HID; j++) p[j] = 0.f;
#pragma unroll
        for (int k = 0; k < HID; k++) {
#pragma unroll
            for (int j = 0; j < HID; j++) p[j] += hn[k] * sWgh[k * HID + j];
        }
#pragma unroll
        for (int j = 0; j < HID; j++) g_P[n * PSTR + j] = p[j];
    }
}

// ---------------------------------------------------------------------------
extern "C" void kernel_launch(void* const* d_in, const int* in_sizes, int n_in,
                              void* d_out, int out_size)
{
    const float* vertex = (const float*)d_in[0];
    const float* ef     = (const float*)d_in[1];
    const int*   src    = (const int*)d_in[2];
    const int*   dst    = (const int*)d_in[3];
    const float* Wi     = (const float*)d_in[4];
    const float* Wg     = (const float*)d_in[5];
    const float* Wu     = (const float*)d_in[6];
    float* out = (float*)d_out;

    init_kernel<<<(NN + 127) / 128, 128>>>(vertex, Wi, Wg);

    const int zblocks = (NN * PSTR / 4 + 255) / 256;
    const int eblocks = 148 * 8;  // grid-stride: ~21 edges/thread, weight regs amortized

    for (int depth = 0; depth < 2; depth++) {
        zero_agg_kernel<<<zblocks, 256>>>();
        edge_kernel<<<eblocks, 256>>>(ef, src, dst, Wg);
        update_kernel<<<(NN + 255) / 256, 256>>>(Wu, Wg, out, depth == 1);
    }
}